// round 6
// baseline (speedup 1.0000x reference)
#include <cuda_runtime.h>
#include <math.h>

#define NN   50000
#define NE   800000
#define NF   100
#define TDIM 100
#define TBL  8192
#define EPW  8          // edges per warp (dot kernel)
#define NPW  4          // nodes per warp

// ---------------- scratch (static __device__, no allocation) ----------------
__device__ float4 g_wl0[25], g_wl1[25], g_wr0[25], g_wr1[25];   // node attn-folded weights
__device__ float4 g_we0[25], g_we1[25];                         // edge raw-feature folded weights
__device__ float  g_weT0[TDIM], g_weT1[TDIM];                   // temporal folded weights
__device__ float  g_bl[2], g_br[2], g_be[2];
__device__ float4 g_tbl[TBL + 1];                               // {g0(x), g1(x), dg0, dg1} (b_e baked in)
__device__ float4 g_elts[NN];                                   // {el0, el1, node_ts, 0}
__device__ float2 g_er[NN];
__device__ float4 g_acc[NN];                                    // {den0, num0, den1, num1}
__device__ float2 g_ee[NE];                                     // per-edge raw-feature dot (both heads)

// ---------------- pass 0: fold attention vectors into fc weights ------------
__global__ void prep_kernel(const float* __restrict__ fc_node_w,
                            const float* __restrict__ fc_node_b,
                            const float* __restrict__ fc_edge_w,
                            const float* __restrict__ fc_edge_b,
                            const float* __restrict__ attn_l,
                            const float* __restrict__ attn_r,
                            const float* __restrict__ attn_e) {
    int t = blockIdx.x * blockDim.x + threadIdx.x;
    if (t >= 806) return;
    if (t < 200) {                                   // w_l [100][2]
        int k = t >> 1, h = t & 1;
        const float* wr = fc_node_w + k * 200 + h * 100;
        const float* a  = attn_l + h * 100;
        float s = 0.f;
        for (int f = 0; f < 100; f++) s += wr[f] * a[f];
        ((float*)(h ? g_wl1 : g_wl0))[k] = s;
    } else if (t < 400) {                            // w_r [100][2]
        int k = (t - 200) >> 1, h = t & 1;
        const float* wr = fc_node_w + k * 200 + h * 100;
        const float* a  = attn_r + h * 100;
        float s = 0.f;
        for (int f = 0; f < 100; f++) s += wr[f] * a[f];
        ((float*)(h ? g_wr1 : g_wr0))[k] = s;
    } else if (t < 800) {                            // w_e [200][2]
        int k = (t - 400) >> 1, h = t & 1;
        const float* wr = fc_edge_w + k * 200 + h * 100;
        const float* a  = attn_e + h * 100;
        float s = 0.f;
        for (int f = 0; f < 100; f++) s += wr[f] * a[f];
        if (k < 100) ((float*)(h ? g_we1 : g_we0))[k] = s;
        else         (h ? g_weT1 : g_weT0)[k - 100] = s;
    } else {                                         // biases folded
        int u = t - 800, h = u & 1;
        float s = 0.f;
        if (u < 2)      { for (int f = 0; f < 100; f++) s += fc_node_b[h*100+f] * attn_l[h*100+f]; g_bl[h] = s; }
        else if (u < 4) { for (int f = 0; f < 100; f++) s += fc_node_b[h*100+f] * attn_r[h*100+f]; g_br[h] = s; }
        else            { for (int f = 0; f < 100; f++) s += fc_edge_b[h*100+f] * attn_e[h*100+f]; g_be[h] = s; }
    }
}

// ---------------- pass 0b: temporal lookup table ----------------------------
__global__ void table_kernel(const float* __restrict__ time_w,
                             const float* __restrict__ time_b) {
    int i = blockIdx.x * blockDim.x + threadIdx.x;
    if (i > TBL) return;
    const float dx = 2.0f / (float)TBL;
    float x  = -1.0f + i * dx;
    float x2 = x + dx;
    float v0 = 0.f, v1 = 0.f, u0 = 0.f, u1 = 0.f;
    for (int j = 0; j < TDIM; j++) {
        float w = time_w[j], b = time_b[j];
        float c  = cosf(x  * w + b);
        float c2 = cosf(x2 * w + b);
        float e0 = g_weT0[j], e1 = g_weT1[j];
        v0 += c  * e0; v1 += c  * e1;
        u0 += c2 * e0; u1 += c2 * e1;
    }
    float b0 = g_be[0], b1 = g_be[1];
    g_tbl[i] = make_float4(v0 + b0, v1 + b1, u0 - v0, u1 - v1);
}

// ---------------- pass 1: per-node el/er + acc zero (4 nodes per warp) ------
__global__ void node_kernel(const float* __restrict__ memory,
                            const float* __restrict__ node_ts) {
    int warp = (blockIdx.x * blockDim.x + threadIdx.x) >> 5;
    int lane = threadIdx.x & 31;
    int n0 = warp * NPW;
    if (n0 >= NN) return;
    float4 z = make_float4(0.f, 0.f, 0.f, 0.f);
    float4 wl0 = z, wl1 = z, wr0 = z, wr1 = z;
    if (lane < 25) { wl0 = g_wl0[lane]; wl1 = g_wl1[lane];
                     wr0 = g_wr0[lane]; wr1 = g_wr1[lane]; }
    float4 m[NPW];
    #pragma unroll
    for (int j = 0; j < NPW; j++)
        m[j] = (lane < 25) ? ((const float4*)(memory + (size_t)(n0 + j) * NF))[lane] : z;

    float l0[NPW], l1[NPW], r0[NPW], r1[NPW];
    #pragma unroll
    for (int j = 0; j < NPW; j++) {
        l0[j] = m[j].x*wl0.x + m[j].y*wl0.y + m[j].z*wl0.z + m[j].w*wl0.w;
        l1[j] = m[j].x*wl1.x + m[j].y*wl1.y + m[j].z*wl1.z + m[j].w*wl1.w;
        r0[j] = m[j].x*wr0.x + m[j].y*wr0.y + m[j].z*wr0.z + m[j].w*wr0.w;
        r1[j] = m[j].x*wr1.x + m[j].y*wr1.y + m[j].z*wr1.z + m[j].w*wr1.w;
    }
    #pragma unroll
    for (int o = 16; o; o >>= 1)
        #pragma unroll
        for (int j = 0; j < NPW; j++) {
            l0[j] += __shfl_xor_sync(0xffffffffu, l0[j], o);
            l1[j] += __shfl_xor_sync(0xffffffffu, l1[j], o);
            r0[j] += __shfl_xor_sync(0xffffffffu, r0[j], o);
            r1[j] += __shfl_xor_sync(0xffffffffu, r1[j], o);
        }
    if (lane < NPW) {
        float vl0 = l0[0], vl1 = l1[0], vr0 = r0[0], vr1 = r1[0];
        #pragma unroll
        for (int j = 1; j < NPW; j++)
            if (lane == j) { vl0 = l0[j]; vl1 = l1[j]; vr0 = r0[j]; vr1 = r1[j]; }
        int n = n0 + lane;
        float ts = node_ts[n];
        g_elts[n] = make_float4(vl0 + g_bl[0], vl1 + g_bl[1], ts, 0.f);
        g_er[n]   = make_float2(vr0 + g_br[0], vr1 + g_br[1]);
        g_acc[n]  = make_float4(0.f, 0.f, 0.f, 0.f);
    }
}

// ---------------- pass 2a: edge raw-feature dots (pure streaming) -----------
__global__ void edge_dot_kernel(const float* __restrict__ raw) {
    int warp = (blockIdx.x * blockDim.x + threadIdx.x) >> 5;
    int lane = threadIdx.x & 31;
    long e0 = (long)warp * EPW;
    if (e0 >= NE) return;

    float4 z = make_float4(0.f, 0.f, 0.f, 0.f);
    float4 w0 = z, w1 = z;
    if (lane < 25) { w0 = g_we0[lane]; w1 = g_we1[lane]; }

    float4 r[EPW];
    #pragma unroll
    for (int j = 0; j < EPW; j++)
        r[j] = (lane < 25) ? ((const float4*)(raw + (e0 + j) * NF))[lane] : z;

    float a0[EPW], a1[EPW];
    #pragma unroll
    for (int j = 0; j < EPW; j++) {
        a0[j] = r[j].x*w0.x + r[j].y*w0.y + r[j].z*w0.z + r[j].w*w0.w;
        a1[j] = r[j].x*w1.x + r[j].y*w1.y + r[j].z*w1.z + r[j].w*w1.w;
    }
    #pragma unroll
    for (int o = 16; o; o >>= 1)
        #pragma unroll
        for (int j = 0; j < EPW; j++) {
            a0[j] += __shfl_xor_sync(0xffffffffu, a0[j], o);
            a1[j] += __shfl_xor_sync(0xffffffffu, a1[j], o);
        }
    if (lane < EPW) {
        float av0 = a0[0], av1 = a1[0];
        #pragma unroll
        for (int j = 1; j < EPW; j++)
            if (lane == j) { av0 = a0[j]; av1 = a1[j]; }
        g_ee[e0 + lane] = make_float2(av0, av1);
    }
}

// ---------------- pass 2b: edge scatter (thread per edge) -------------------
__global__ void edge_scatter_kernel(const float* __restrict__ edge_ts,
                                    const int*   __restrict__ src,
                                    const int*   __restrict__ dst) {
    int e = blockIdx.x * blockDim.x + threadIdx.x;
    if (e >= NE) return;
    float2 ee  = g_ee[e];
    int s = src[e], d = dst[e];
    float  ets = edge_ts[e];
    float4 el4 = g_elts[s];                        // {el0, el1, ts_s, 0}
    float2 er2 = g_er[d];
    float td = ets - el4.z;
    float u  = (td + 1.0f) * ((float)TBL * 0.5f);
    u = fminf(fmaxf(u, 0.0f), (float)TBL - 0.001f);
    int   i  = (int)u;
    float fr = u - (float)i;
    float4 t = g_tbl[i];
    float elp0 = el4.x + ee.x + fmaf(t.z, fr, t.x);   // el_prime head 0 (b_e baked in table)
    float elp1 = el4.y + ee.y + fmaf(t.w, fr, t.y);   // el_prime head 1
    float ev0 = elp0 + er2.x;
    float ev1 = elp1 + er2.y;
    ev0 = ev0 > 0.f ? ev0 : 0.2f * ev0;               // leaky relu
    ev1 = ev1 > 0.f ? ev1 : 0.2f * ev1;
    float p0 = __expf(ev0);
    float p1 = __expf(ev1);
    float n0v = p0 * elp0;
    float n1v = p1 * elp1;
    asm volatile("red.global.add.v4.f32 [%0], {%1, %2, %3, %4};"
                 :: "l"(&g_acc[d]), "f"(p0), "f"(n0v), "f"(p1), "f"(n1v)
                 : "memory");
}

// ---------------- pass 3: output (float4 per thread) ------------------------
__global__ void out_kernel(const float4* __restrict__ mem4, float4* __restrict__ out4) {
    int idx = blockIdx.x * blockDim.x + threadIdx.x;
    if (idx >= NN * (NF / 4)) return;
    int n = idx / (NF / 4);
    float4 acc = g_acc[n];
    float ft = (acc.x > 0.f ? acc.y / acc.x : 0.f)
             + (acc.z > 0.f ? acc.w / acc.z : 0.f);
    float add = 0.5f * ft;
    float4 m = mem4[idx];
    out4[idx] = make_float4(m.x + add, m.y + add, m.z + add, m.w + add);
}

// ---------------- launch -----------------------------------------------------
extern "C" void kernel_launch(void* const* d_in, const int* in_sizes, int n_in,
                              void* d_out, int out_size) {
    const float* memory    = (const float*)d_in[0];
    const float* node_ts   = (const float*)d_in[1];
    const float* raw       = (const float*)d_in[2];
    const float* edge_ts   = (const float*)d_in[3];
    const float* time_w    = (const float*)d_in[4];
    const float* time_b    = (const float*)d_in[5];
    const float* fc_node_w = (const float*)d_in[6];
    const float* fc_node_b = (const float*)d_in[7];
    const float* fc_edge_w = (const float*)d_in[8];
    const float* fc_edge_b = (const float*)d_in[9];
    const float* attn_l    = (const float*)d_in[10];
    const float* attn_r    = (const float*)d_in[11];
    const float* attn_e    = (const float*)d_in[12];
    const int*   src       = (const int*)d_in[13];
    const int*   dst       = (const int*)d_in[14];
    float* out = (float*)d_out;

    prep_kernel<<<7, 128>>>(fc_node_w, fc_node_b, fc_edge_w, fc_edge_b,
                            attn_l, attn_r, attn_e);
    table_kernel<<<(TBL + 1 + 255) / 256, 256>>>(time_w, time_b);
    node_kernel<<<((NN / NPW) * 32 + 255) / 256, 256>>>(memory, node_ts);
    edge_dot_kernel<<<((NE / EPW) * 32) / 256, 256>>>(raw);
    edge_scatter_kernel<<<(NE + 255) / 256, 256>>>(edge_ts, src, dst);
    out_kernel<<<(NN * (NF / 4) + 255) / 256, 256>>>((const float4*)memory, (float4*)out);
}

// round 9
// speedup vs baseline: 1.1136x; 1.1136x over previous
#include <cuda_runtime.h>
#include <cstdint>
#include <math.h>

#define NN   50000
#define NE   800000
#define NF   100
#define TDIM 100
#define TBL  8192
#define EPB  64         // edges per block (staged)
#define NPB  64         // nodes per block (staged)

// ---------------- scratch (static __device__, no allocation) ----------------
__device__ float4 g_wl0[25], g_wl1[25], g_wr0[25], g_wr1[25];   // node attn-folded weights
__device__ float4 g_we0[25], g_we1[25];                         // edge raw-feature folded weights
__device__ float  g_weT0[TDIM], g_weT1[TDIM];                   // temporal folded weights
__device__ float  g_bl[2], g_br[2], g_be[2];
__device__ float4 g_tbl[TBL + 1];                               // {g0, g1, dg0, dg1} (b_e baked in)
__device__ float4 g_elts[NN];                                   // {el0, el1, node_ts, 0}
__device__ float2 g_er[NN];
__device__ float4 g_acc[NN];                                    // {den0, num0, den1, num1}

__device__ __forceinline__ void cp16(unsigned int dst, const void* src) {
    asm volatile("cp.async.cg.shared.global [%0], [%1], 16;" :: "r"(dst), "l"(src));
}
__device__ __forceinline__ void cp_commit_wait() {
    asm volatile("cp.async.commit_group;");
    asm volatile("cp.async.wait_group 0;" ::: "memory");
}

// ---------------- pass 0: fold attention vectors into fc weights ------------
__global__ void prep_kernel(const float* __restrict__ fc_node_w,
                            const float* __restrict__ fc_node_b,
                            const float* __restrict__ fc_edge_w,
                            const float* __restrict__ fc_edge_b,
                            const float* __restrict__ attn_l,
                            const float* __restrict__ attn_r,
                            const float* __restrict__ attn_e) {
    int t = blockIdx.x * blockDim.x + threadIdx.x;
    if (t >= 806) return;
    if (t < 200) {                                   // w_l [100][2]
        int k = t >> 1, h = t & 1;
        const float* wr = fc_node_w + k * 200 + h * 100;
        const float* a  = attn_l + h * 100;
        float s = 0.f;
        for (int f = 0; f < 100; f++) s += wr[f] * a[f];
        ((float*)(h ? g_wl1 : g_wl0))[k] = s;
    } else if (t < 400) {                            // w_r [100][2]
        int k = (t - 200) >> 1, h = t & 1;
        const float* wr = fc_node_w + k * 200 + h * 100;
        const float* a  = attn_r + h * 100;
        float s = 0.f;
        for (int f = 0; f < 100; f++) s += wr[f] * a[f];
        ((float*)(h ? g_wr1 : g_wr0))[k] = s;
    } else if (t < 800) {                            // w_e [200][2]
        int k = (t - 400) >> 1, h = t & 1;
        const float* wr = fc_edge_w + k * 200 + h * 100;
        const float* a  = attn_e + h * 100;
        float s = 0.f;
        for (int f = 0; f < 100; f++) s += wr[f] * a[f];
        if (k < 100) ((float*)(h ? g_we1 : g_we0))[k] = s;
        else         (h ? g_weT1 : g_weT0)[k - 100] = s;
    } else {                                         // biases folded
        int u = t - 800, h = u & 1;
        float s = 0.f;
        if (u < 2)      { for (int f = 0; f < 100; f++) s += fc_node_b[h*100+f] * attn_l[h*100+f]; g_bl[h] = s; }
        else if (u < 4) { for (int f = 0; f < 100; f++) s += fc_node_b[h*100+f] * attn_r[h*100+f]; g_br[h] = s; }
        else            { for (int f = 0; f < 100; f++) s += fc_edge_b[h*100+f] * attn_e[h*100+f]; g_be[h] = s; }
    }
}

// ---------------- pass 0b: temporal lookup table ----------------------------
__global__ void table_kernel(const float* __restrict__ time_w,
                             const float* __restrict__ time_b) {
    int i = blockIdx.x * blockDim.x + threadIdx.x;
    if (i > TBL) return;
    const float dx = 2.0f / (float)TBL;
    float x  = -1.0f + i * dx;
    float x2 = x + dx;
    float v0 = 0.f, v1 = 0.f, u0 = 0.f, u1 = 0.f;
    for (int j = 0; j < TDIM; j++) {
        float w = time_w[j], b = time_b[j];
        float c  = cosf(x  * w + b);
        float c2 = cosf(x2 * w + b);
        float e0 = g_weT0[j], e1 = g_weT1[j];
        v0 += c  * e0; v1 += c  * e1;
        u0 += c2 * e0; u1 += c2 * e1;
    }
    float b0 = g_be[0], b1 = g_be[1];
    g_tbl[i] = make_float4(v0 + b0, v1 + b1, u0 - v0, u1 - v1);
}

// ---------------- pass 1: node el/er + acc zero (staged, 64 nodes/block) ----
__global__ void __launch_bounds__(256) node_kernel(const float* __restrict__ memory,
                                                   const float* __restrict__ node_ts) {
    __shared__ float4 tile[NPB * 25];                // 25.6 KB
    __shared__ float4 swl0[25], swl1[25], swr0[25], swr1[25];
    int tid = threadIdx.x;
    int n0  = blockIdx.x * NPB;
    int rem = NN - n0; if (rem > NPB) rem = NPB;
    int lim = rem * 25;

    if (tid < 25)       swl0[tid]      = g_wl0[tid];
    else if (tid < 50)  swl1[tid - 25] = g_wl1[tid - 25];
    else if (tid < 75)  swr0[tid - 50] = g_wr0[tid - 50];
    else if (tid < 100) swr1[tid - 75] = g_wr1[tid - 75];

    const float4* g = (const float4*)memory + (size_t)n0 * 25;
    unsigned int sb = (unsigned int)__cvta_generic_to_shared(tile);
    #pragma unroll
    for (int k = 0; k < 7; k++) {                    // ceil(64*25/256)=7
        int idx = tid + 256 * k;
        if (idx < lim) cp16(sb + idx * 16, g + idx);
    }
    cp_commit_wait();
    __syncthreads();

    int e = tid >> 2;                 // local node
    int q = tid & 3;
    int j0  = q * 6 + (q ? 1 : 0);    // 0,7,13,19
    int cnt = q ? 6 : 7;
    float l0 = 0.f, l1 = 0.f, r0 = 0.f, r1 = 0.f;
    const float4* row = tile + e * 25;
    for (int i = 0; i < cnt; i++) {
        float4 m = row[j0 + i];
        float4 w = swl0[j0 + i]; l0 += m.x*w.x + m.y*w.y + m.z*w.z + m.w*w.w;
        w = swl1[j0 + i];        l1 += m.x*w.x + m.y*w.y + m.z*w.z + m.w*w.w;
        w = swr0[j0 + i];        r0 += m.x*w.x + m.y*w.y + m.z*w.z + m.w*w.w;
        w = swr1[j0 + i];        r1 += m.x*w.x + m.y*w.y + m.z*w.z + m.w*w.w;
    }
    #pragma unroll
    for (int o = 1; o <= 2; o <<= 1) {
        l0 += __shfl_xor_sync(0xffffffffu, l0, o);
        l1 += __shfl_xor_sync(0xffffffffu, l1, o);
        r0 += __shfl_xor_sync(0xffffffffu, r0, o);
        r1 += __shfl_xor_sync(0xffffffffu, r1, o);
    }
    if (q == 0 && e < rem) {
        int n = n0 + e;
        float ts = node_ts[n];
        g_elts[n] = make_float4(l0 + g_bl[0], l1 + g_bl[1], ts, 0.f);
        g_er[n]   = make_float2(r0 + g_br[0], r1 + g_br[1]);
        g_acc[n]  = make_float4(0.f, 0.f, 0.f, 0.f);
    }
}

// ---------------- pass 2: edge sweep (staged GEMV + fused scatter) ----------
__global__ void __launch_bounds__(256) edge_kernel(const float* __restrict__ raw,
                                                   const float* __restrict__ edge_ts,
                                                   const int*   __restrict__ src,
                                                   const int*   __restrict__ dst) {
    __shared__ float4 tile[EPB * 25];                // 25.6 KB
    __shared__ float4 sw0[25], sw1[25];
    int tid = threadIdx.x;
    int e0  = blockIdx.x * EPB;

    if (tid < 25)      sw0[tid]      = g_we0[tid];
    else if (tid < 50) sw1[tid - 25] = g_we1[tid - 25];

    const float4* g = (const float4*)raw + (size_t)e0 * 25;
    unsigned int sb = (unsigned int)__cvta_generic_to_shared(tile);
    #pragma unroll
    for (int k = 0; k < 7; k++) {                    // ceil(64*25/256)=7
        int idx = tid + 256 * k;
        if (idx < EPB * 25) cp16(sb + idx * 16, g + idx);
    }
    cp_commit_wait();
    __syncthreads();

    int e = tid >> 2;                 // local edge
    int q = tid & 3;
    int j0  = q * 6 + (q ? 1 : 0);    // 0,7,13,19
    int cnt = q ? 6 : 7;
    float a0 = 0.f, a1 = 0.f;
    const float4* row = tile + e * 25;
    for (int i = 0; i < cnt; i++) {
        float4 r = row[j0 + i];
        float4 w = sw0[j0 + i]; a0 += r.x*w.x + r.y*w.y + r.z*w.z + r.w*w.w;
        w = sw1[j0 + i];        a1 += r.x*w.x + r.y*w.y + r.z*w.z + r.w*w.w;
    }
    a0 += __shfl_xor_sync(0xffffffffu, a0, 1);
    a1 += __shfl_xor_sync(0xffffffffu, a1, 1);
    a0 += __shfl_xor_sync(0xffffffffu, a0, 2);
    a1 += __shfl_xor_sync(0xffffffffu, a1, 2);

    if (q == 0) {                     // fused scatter tail (8 lanes/warp)
        int eg = e0 + e;
        int s = src[eg], d = dst[eg];
        float ets = edge_ts[eg];
        float4 el4 = g_elts[s];                       // {el0, el1, ts_s, 0}
        float2 er2 = g_er[d];
        float td = ets - el4.z;
        float u  = (td + 1.0f) * ((float)TBL * 0.5f);
        u = fminf(fmaxf(u, 0.0f), (float)TBL - 0.001f);
        int   i  = (int)u;
        float fr = u - (float)i;
        float4 t = g_tbl[i];
        float elp0 = el4.x + a0 + fmaf(t.z, fr, t.x); // el_prime head 0 (b_e in table)
        float elp1 = el4.y + a1 + fmaf(t.w, fr, t.y); // el_prime head 1
        float ev0 = elp0 + er2.x;
        float ev1 = elp1 + er2.y;
        ev0 = ev0 > 0.f ? ev0 : 0.2f * ev0;           // leaky relu
        ev1 = ev1 > 0.f ? ev1 : 0.2f * ev1;
        float p0 = __expf(ev0);
        float p1 = __expf(ev1);
        float n0v = p0 * elp0;
        float n1v = p1 * elp1;
        asm volatile("red.global.add.v4.f32 [%0], {%1, %2, %3, %4};"
                     :: "l"(&g_acc[d]), "f"(p0), "f"(n0v), "f"(p1), "f"(n1v)
                     : "memory");
    }
}

// ---------------- pass 3: output (float4 per thread) ------------------------
__global__ void out_kernel(const float4* __restrict__ mem4, float4* __restrict__ out4) {
    int idx = blockIdx.x * blockDim.x + threadIdx.x;
    if (idx >= NN * (NF / 4)) return;
    int n = idx / (NF / 4);
    float4 acc = g_acc[n];
    float ft = (acc.x > 0.f ? acc.y / acc.x : 0.f)
             + (acc.z > 0.f ? acc.w / acc.z : 0.f);
    float add = 0.5f * ft;
    float4 m = mem4[idx];
    out4[idx] = make_float4(m.x + add, m.y + add, m.z + add, m.w + add);
}

// ---------------- launch -----------------------------------------------------
extern "C" void kernel_launch(void* const* d_in, const int* in_sizes, int n_in,
                              void* d_out, int out_size) {
    const float* memory    = (const float*)d_in[0];
    const float* node_ts   = (const float*)d_in[1];
    const float* raw       = (const float*)d_in[2];
    const float* edge_ts   = (const float*)d_in[3];
    const float* time_w    = (const float*)d_in[4];
    const float* time_b    = (const float*)d_in[5];
    const float* fc_node_w = (const float*)d_in[6];
    const float* fc_node_b = (const float*)d_in[7];
    const float* fc_edge_w = (const float*)d_in[8];
    const float* fc_edge_b = (const float*)d_in[9];
    const float* attn_l    = (const float*)d_in[10];
    const float* attn_r    = (const float*)d_in[11];
    const float* attn_e    = (const float*)d_in[12];
    const int*   src       = (const int*)d_in[13];
    const int*   dst       = (const int*)d_in[14];
    float* out = (float*)d_out;

    prep_kernel<<<7, 128>>>(fc_node_w, fc_node_b, fc_edge_w, fc_edge_b,
                            attn_l, attn_r, attn_e);
    table_kernel<<<(TBL + 1 + 255) / 256, 256>>>(time_w, time_b);
    node_kernel<<<(NN + NPB - 1) / NPB, 256>>>(memory, node_ts);
    edge_kernel<<<NE / EPB, 256>>>(raw, edge_ts, src, dst);
    out_kernel<<<(NN * (NF / 4) + 255) / 256, 256>>>((const float4*)memory, (float4*)out);
}

// round 10
// speedup vs baseline: 1.3513x; 1.2135x over previous
#include <cuda_runtime.h>
#include <cstdint>
#include <math.h>

#define NN   50000
#define NE   800000
#define NF   100
#define TDIM 100
#define TBL  8192
#define EPB  64         // edges per block (staged)
#define NPB  64         // nodes per block (staged)

// ---------------- scratch (static __device__, no allocation) ----------------
__device__ float4 g_wl0[25], g_wl1[25], g_wr0[25], g_wr1[25];   // node attn-folded weights
__device__ float4 g_we0[25], g_we1[25];                         // edge raw-feature folded weights
__device__ float  g_weT0[TDIM], g_weT1[TDIM];                   // temporal folded weights
__device__ float  g_bl[2], g_br[2], g_be[2];
__device__ float4 g_tbl[TBL + 1];                               // {g0, g1, dg0, dg1} (b_e baked in)
__device__ float4 g_elts[NN];                                   // {el0, el1, node_ts, 0}
__device__ float2 g_er[NN];
__device__ float4 g_acc[NN];                                    // {den0, num0, den1, num1}

__device__ __forceinline__ void mbar_init(unsigned long long* mbar) {
    unsigned m = (unsigned)__cvta_generic_to_shared(mbar);
    asm volatile("mbarrier.init.shared.b64 [%0], 1;" :: "r"(m) : "memory");
}
__device__ __forceinline__ void bulk_ld(void* dst_smem, const void* src,
                                        unsigned bytes, unsigned long long* mbar) {
    unsigned d = (unsigned)__cvta_generic_to_shared(dst_smem);
    unsigned m = (unsigned)__cvta_generic_to_shared(mbar);
    asm volatile("mbarrier.arrive.expect_tx.shared.b64 _, [%0], %1;" :: "r"(m), "r"(bytes) : "memory");
    asm volatile("cp.async.bulk.shared::cluster.global.mbarrier::complete_tx::bytes [%0], [%1], %2, [%3];"
                 :: "r"(d), "l"(src), "r"(bytes), "r"(m) : "memory");
}
__device__ __forceinline__ void mbar_wait(unsigned long long* mbar) {
    unsigned m = (unsigned)__cvta_generic_to_shared(mbar);
    asm volatile(
        "{\n\t"
        ".reg .pred P;\n\t"
        "W%=:\n\t"
        "mbarrier.try_wait.parity.acquire.cta.shared::cta.b64 P, [%0], 0, 0x989680;\n\t"
        "@P bra D%=;\n\t"
        "bra W%=;\n\t"
        "D%=:\n\t"
        "}" :: "r"(m) : "memory");
}

// ---------------- pass 0: fold attention vectors into fc weights ------------
__global__ void prep_kernel(const float* __restrict__ fc_node_w,
                            const float* __restrict__ fc_node_b,
                            const float* __restrict__ fc_edge_w,
                            const float* __restrict__ fc_edge_b,
                            const float* __restrict__ attn_l,
                            const float* __restrict__ attn_r,
                            const float* __restrict__ attn_e) {
    int t = blockIdx.x * blockDim.x + threadIdx.x;
    if (t >= 806) return;
    if (t < 800) {
        int base = (t < 200) ? 0 : (t < 400 ? 200 : 400);
        int u = t - base;
        int k = u >> 1, h = u & 1;
        const float4* wr;
        const float4* a;
        if (t < 200)      { wr = (const float4*)(fc_node_w + k * 200 + h * 100); a = (const float4*)(attn_l + h * 100); }
        else if (t < 400) { wr = (const float4*)(fc_node_w + k * 200 + h * 100); a = (const float4*)(attn_r + h * 100); }
        else              { wr = (const float4*)(fc_edge_w + k * 200 + h * 100); a = (const float4*)(attn_e + h * 100); }
        float s = 0.f;
        #pragma unroll
        for (int f = 0; f < 25; f++) {
            float4 wv = wr[f], av = a[f];
            s += wv.x*av.x + wv.y*av.y + wv.z*av.z + wv.w*av.w;
        }
        if (t < 200)      ((float*)(h ? g_wl1 : g_wl0))[k] = s;
        else if (t < 400) ((float*)(h ? g_wr1 : g_wr0))[k] = s;
        else if (k < 100) ((float*)(h ? g_we1 : g_we0))[k] = s;
        else              (h ? g_weT1 : g_weT0)[k - 100] = s;
    } else {
        int u = t - 800, h = u & 1;
        float s = 0.f;
        if (u < 2)      { for (int f = 0; f < 100; f++) s += fc_node_b[h*100+f] * attn_l[h*100+f]; g_bl[h] = s; }
        else if (u < 4) { for (int f = 0; f < 100; f++) s += fc_node_b[h*100+f] * attn_r[h*100+f]; g_br[h] = s; }
        else            { for (int f = 0; f < 100; f++) s += fc_edge_b[h*100+f] * attn_e[h*100+f]; g_be[h] = s; }
    }
}

// ---------------- pass 0b: temporal lookup table ----------------------------
__global__ void table_kernel(const float* __restrict__ time_w,
                             const float* __restrict__ time_b) {
    int i = blockIdx.x * blockDim.x + threadIdx.x;
    if (i > TBL) return;
    const float dx = 2.0f / (float)TBL;
    float x  = -1.0f + i * dx;
    float x2 = x + dx;
    float v0 = 0.f, v1 = 0.f, u0 = 0.f, u1 = 0.f;
    for (int j = 0; j < TDIM; j++) {
        float w = time_w[j], b = time_b[j];
        float c  = __cosf(fmaf(x,  w, b));
        float c2 = __cosf(fmaf(x2, w, b));
        float e0 = g_weT0[j], e1 = g_weT1[j];
        v0 += c  * e0; v1 += c  * e1;
        u0 += c2 * e0; u1 += c2 * e1;
    }
    float b0 = g_be[0], b1 = g_be[1];
    g_tbl[i] = make_float4(v0 + b0, v1 + b1, u0 - v0, u1 - v1);
}

// ---------------- pass 1: node el/er + acc zero (bulk-staged) ---------------
__global__ void __launch_bounds__(256) node_kernel(const float* __restrict__ memory,
                                                   const float* __restrict__ node_ts) {
    __shared__ __align__(128) float4 tile[NPB * 25];   // 25.6 KB
    __shared__ float4 swl0[25], swl1[25], swr0[25], swr1[25];
    __shared__ unsigned long long mbar;
    int tid = threadIdx.x;
    int n0  = blockIdx.x * NPB;
    int rem = NN - n0; if (rem > NPB) rem = NPB;
    int lim = rem * 25;

    if (tid == 0) mbar_init(&mbar);
    __syncthreads();
    if (tid == 0)
        bulk_ld(tile, (const float4*)memory + (size_t)n0 * 25, lim * 16, &mbar);

    if (tid < 25)       swl0[tid]      = g_wl0[tid];
    else if (tid < 50)  swl1[tid - 25] = g_wl1[tid - 25];
    else if (tid < 75)  swr0[tid - 50] = g_wr0[tid - 50];
    else if (tid < 100) swr1[tid - 75] = g_wr1[tid - 75];

    mbar_wait(&mbar);
    __syncthreads();

    int e = tid >> 2;                 // local node
    int q = tid & 3;
    int j0  = q * 6 + (q ? 1 : 0);    // 0,7,13,19
    int cnt = q ? 6 : 7;
    float l0 = 0.f, l1 = 0.f, r0 = 0.f, r1 = 0.f;
    const float4* row = tile + e * 25;
    for (int i = 0; i < cnt; i++) {
        float4 m = row[j0 + i];
        float4 w = swl0[j0 + i]; l0 += m.x*w.x + m.y*w.y + m.z*w.z + m.w*w.w;
        w = swl1[j0 + i];        l1 += m.x*w.x + m.y*w.y + m.z*w.z + m.w*w.w;
        w = swr0[j0 + i];        r0 += m.x*w.x + m.y*w.y + m.z*w.z + m.w*w.w;
        w = swr1[j0 + i];        r1 += m.x*w.x + m.y*w.y + m.z*w.z + m.w*w.w;
    }
    #pragma unroll
    for (int o = 1; o <= 2; o <<= 1) {
        l0 += __shfl_xor_sync(0xffffffffu, l0, o);
        l1 += __shfl_xor_sync(0xffffffffu, l1, o);
        r0 += __shfl_xor_sync(0xffffffffu, r0, o);
        r1 += __shfl_xor_sync(0xffffffffu, r1, o);
    }
    if (q == 0 && e < rem) {
        int n = n0 + e;
        float ts = node_ts[n];
        g_elts[n] = make_float4(l0 + g_bl[0], l1 + g_bl[1], ts, 0.f);
        g_er[n]   = make_float2(r0 + g_br[0], r1 + g_br[1]);
        g_acc[n]  = make_float4(0.f, 0.f, 0.f, 0.f);
    }
}

// ---------------- pass 2: edge sweep (bulk-staged GEMV + fused scatter) -----
__global__ void __launch_bounds__(256) edge_kernel(const float* __restrict__ raw,
                                                   const float* __restrict__ edge_ts,
                                                   const int*   __restrict__ src,
                                                   const int*   __restrict__ dst) {
    __shared__ __align__(128) float4 tile[EPB * 25];   // 25.6 KB
    __shared__ float4 sw0[25], sw1[25];
    __shared__ unsigned long long mbar;
    int tid = threadIdx.x;
    int e0  = blockIdx.x * EPB;

    if (tid == 0) mbar_init(&mbar);
    __syncthreads();
    if (tid == 0)
        bulk_ld(tile, (const float4*)raw + (size_t)e0 * 25, EPB * 25 * 16, &mbar);

    if (tid < 25)      sw0[tid]      = g_we0[tid];
    else if (tid < 50) sw1[tid - 25] = g_we1[tid - 25];

    mbar_wait(&mbar);
    __syncthreads();

    int e = tid >> 2;                 // local edge
    int q = tid & 3;
    int j0  = q * 6 + (q ? 1 : 0);    // 0,7,13,19
    int cnt = q ? 6 : 7;
    float a0 = 0.f, a1 = 0.f;
    const float4* row = tile + e * 25;
    for (int i = 0; i < cnt; i++) {
        float4 r = row[j0 + i];
        float4 w = sw0[j0 + i]; a0 += r.x*w.x + r.y*w.y + r.z*w.z + r.w*w.w;
        w = sw1[j0 + i];        a1 += r.x*w.x + r.y*w.y + r.z*w.z + r.w*w.w;
    }
    a0 += __shfl_xor_sync(0xffffffffu, a0, 1);
    a1 += __shfl_xor_sync(0xffffffffu, a1, 1);
    a0 += __shfl_xor_sync(0xffffffffu, a0, 2);
    a1 += __shfl_xor_sync(0xffffffffu, a1, 2);

    if (q == 0) {                     // fused scatter tail (8 lanes/warp)
        int eg = e0 + e;
        int s = src[eg], d = dst[eg];
        float ets = edge_ts[eg];
        float4 el4 = g_elts[s];                       // {el0, el1, ts_s, 0}
        float2 er2 = g_er[d];
        float td = ets - el4.z;
        float u  = (td + 1.0f) * ((float)TBL * 0.5f);
        u = fminf(fmaxf(u, 0.0f), (float)TBL - 0.001f);
        int   i  = (int)u;
        float fr = u - (float)i;
        float4 t = g_tbl[i];
        float elp0 = el4.x + a0 + fmaf(t.z, fr, t.x); // el_prime head 0 (b_e in table)
        float elp1 = el4.y + a1 + fmaf(t.w, fr, t.y); // el_prime head 1
        float ev0 = elp0 + er2.x;
        float ev1 = elp1 + er2.y;
        ev0 = ev0 > 0.f ? ev0 : 0.2f * ev0;           // leaky relu
        ev1 = ev1 > 0.f ? ev1 : 0.2f * ev1;
        float p0 = __expf(ev0);
        float p1 = __expf(ev1);
        float n0v = p0 * elp0;
        float n1v = p1 * elp1;
        asm volatile("red.global.add.v4.f32 [%0], {%1, %2, %3, %4};"
                     :: "l"(&g_acc[d]), "f"(p0), "f"(n0v), "f"(p1), "f"(n1v)
                     : "memory");
    }
}

// ---------------- pass 3: output (float4 per thread) ------------------------
__global__ void out_kernel(const float4* __restrict__ mem4, float4* __restrict__ out4) {
    int idx = blockIdx.x * blockDim.x + threadIdx.x;
    if (idx >= NN * (NF / 4)) return;
    int n = idx / (NF / 4);
    float4 acc = g_acc[n];
    float ft = (acc.x > 0.f ? acc.y / acc.x : 0.f)
             + (acc.z > 0.f ? acc.w / acc.z : 0.f);
    float add = 0.5f * ft;
    float4 m = mem4[idx];
    out4[idx] = make_float4(m.x + add, m.y + add, m.z + add, m.w + add);
}

// ---------------- launch -----------------------------------------------------
extern "C" void kernel_launch(void* const* d_in, const int* in_sizes, int n_in,
                              void* d_out, int out_size) {
    const float* memory    = (const float*)d_in[0];
    const float* node_ts   = (const float*)d_in[1];
    const float* raw       = (const float*)d_in[2];
    const float* edge_ts   = (const float*)d_in[3];
    const float* time_w    = (const float*)d_in[4];
    const float* time_b    = (const float*)d_in[5];
    const float* fc_node_w = (const float*)d_in[6];
    const float* fc_node_b = (const float*)d_in[7];
    const float* fc_edge_w = (const float*)d_in[8];
    const float* fc_edge_b = (const float*)d_in[9];
    const float* attn_l    = (const float*)d_in[10];
    const float* attn_r    = (const float*)d_in[11];
    const float* attn_e    = (const float*)d_in[12];
    const int*   src       = (const int*)d_in[13];
    const int*   dst       = (const int*)d_in[14];
    float* out = (float*)d_out;

    prep_kernel<<<7, 128>>>(fc_node_w, fc_node_b, fc_edge_w, fc_edge_b,
                            attn_l, attn_r, attn_e);
    table_kernel<<<(TBL + 1 + 255) / 256, 256>>>(time_w, time_b);
    node_kernel<<<(NN + NPB - 1) / NPB, 256>>>(memory, node_ts);
    edge_kernel<<<NE / EPB, 256>>>(raw, edge_ts, src, dst);
    out_kernel<<<(NN * (NF / 4) + 255) / 256, 256>>>((const float4*)memory, (float4*)out);
}